// round 1
// baseline (speedup 1.0000x reference)
#include <cuda_runtime.h>

// ---------------- scratch (no allocations allowed) ----------------
__device__ float g_hc[512 * 192];
__device__ float g_AB[512 * 512];    // cols 0..255: A[j]=hc@We0[8:200]; 256..511: B[i]=hc@We0[200:392]
__device__ float g_mi[512 * 256];
__device__ float g_shift[512 * 24];
__device__ float g_phin[512 * 384];
__device__ float g_t0[512 * 256];
__device__ float g_t1[512 * 256];

__device__ __forceinline__ float fsilu(float v) {
    return v * (1.0f / (1.0f + __expf(-v)));
}

// ---------------- init: zero accumulators ----------------
__global__ void k_init() {
    int idx = blockIdx.x * blockDim.x + threadIdx.x;
    int stride = gridDim.x * blockDim.x;
    for (int i = idx; i < 512 * 256; i += stride) g_mi[i] = 0.f;
    for (int i = idx; i < 512 * 24; i += stride) g_shift[i] = 0.f;
}

// ---------------- hc = [h | per-node head-pair sq dists] ----------------
__global__ void k_hc(const float* __restrict__ x, const float* __restrict__ h) {
    int n = blockIdx.x;
    __shared__ float xs[24];
    int tid = threadIdx.x;   // 128 threads
    if (tid < 24) xs[tid] = x[n * 24 + tid];
    __syncthreads();
    g_hc[n * 192 + tid] = h[n * 128 + tid];
    if (tid < 64) {
        int a = tid >> 3, b = tid & 7;
        float dx = xs[a * 3 + 0] - xs[b * 3 + 0];
        float dy = xs[a * 3 + 1] - xs[b * 3 + 1];
        float dz = xs[a * 3 + 2] - xs[b * 3 + 2];
        g_hc[n * 192 + 128 + tid] = dx * dx + dy * dy + dz * dz;
    }
}

// ---------------- generic small GEMM: out = act(A@W + bias) [+ resid] ----------------
// 64x64 tile, 256 threads, 4x4 micro. M,N multiples of 64; K multiple of 16.
__global__ void gemm64(const float* __restrict__ A, int lda,
                       const float* __restrict__ W, int ldw,
                       const float* __restrict__ bias,
                       const float* __restrict__ resid, int ldr,
                       float* __restrict__ out, int ldc,
                       int M, int N, int K, int act) {
    __shared__ float As[16][68];
    __shared__ float Bs[16][68];
    int m0 = blockIdx.y * 64, n0 = blockIdx.x * 64;
    int tid = threadIdx.x;
    int tm = tid >> 4, tn = tid & 15;
    float acc[4][4] = {};
    for (int k0 = 0; k0 < K; k0 += 16) {
#pragma unroll
        for (int u = 0; u < 4; u++) {
            int idx = tid + u * 256;
            int m = idx >> 4, kk = idx & 15;
            As[kk][m] = A[(m0 + m) * lda + k0 + kk];
            int kk2 = idx >> 6, c = idx & 63;
            Bs[kk2][c] = W[(k0 + kk2) * ldw + n0 + c];
        }
        __syncthreads();
#pragma unroll
        for (int kk = 0; kk < 16; kk++) {
            float a[4], b[4];
#pragma unroll
            for (int i = 0; i < 4; i++) a[i] = As[kk][tm * 4 + i];
#pragma unroll
            for (int i = 0; i < 4; i++) b[i] = Bs[kk][tn * 4 + i];
#pragma unroll
            for (int i = 0; i < 4; i++)
#pragma unroll
                for (int j = 0; j < 4; j++) acc[i][j] = fmaf(a[i], b[j], acc[i][j]);
        }
        __syncthreads();
    }
#pragma unroll
    for (int i = 0; i < 4; i++) {
        int row = m0 + tm * 4 + i;
#pragma unroll
        for (int j = 0; j < 4; j++) {
            int col = n0 + tn * 4 + j;
            float v = acc[i][j];
            if (bias) v += bias[col];
            if (act) v = fsilu(v);
            if (resid) v += resid[row * ldr + col];
            out[row * ldc + col] = v;
        }
    }
}

// ---------------- fused edge kernel ----------------
// tile: 8 i x 16 j = 128 edges, 512 threads. warp = 8-edge block; lane covers cols lane+32*jj.
#define XS_LD 260
#define EDGE_SMEM_FLOATS 49696

__device__ __forceinline__ void gemm_tile(const float* __restrict__ Wg,
                                          const float* __restrict__ Xs,
                                          float* __restrict__ Ws,
                                          float (&acc)[8][8],
                                          int tid, int lane, int xrow) {
#pragma unroll
    for (int r = 0; r < 8; r++)
#pragma unroll
        for (int jj = 0; jj < 8; jj++) acc[r][jj] = 0.f;
    for (int kt = 0; kt < 8; ++kt) {
        __syncthreads();
        const float4* src = reinterpret_cast<const float4*>(Wg) + kt * 2048;
        float4* dst = reinterpret_cast<float4*>(Ws);
#pragma unroll
        for (int u = 0; u < 4; u++) dst[tid + u * 512] = src[tid + u * 512];
        __syncthreads();
#pragma unroll 4
        for (int kk = 0; kk < 32; kk++) {
            float a[8], b[8];
#pragma unroll
            for (int jj = 0; jj < 8; jj++) b[jj] = Ws[kk * 256 + lane + 32 * jj];
            int k = kt * 32 + kk;
#pragma unroll
            for (int r = 0; r < 8; r++) a[r] = Xs[(xrow + r) * XS_LD + k];
#pragma unroll
            for (int r = 0; r < 8; r++)
#pragma unroll
                for (int jj = 0; jj < 8; jj++) acc[r][jj] = fmaf(a[r], b[jj], acc[r][jj]);
        }
    }
}

__global__ __launch_bounds__(512) void k_edge(
    const float* __restrict__ x,
    const float* __restrict__ We0, const float* __restrict__ be0,
    const float* __restrict__ We1, const float* __restrict__ be1,
    const float* __restrict__ Winf, const float* __restrict__ binf,
    const float* __restrict__ Wx0, const float* __restrict__ bx0,
    const float* __restrict__ Wx1, const float* __restrict__ bx1,
    const float* __restrict__ Wxo, const float* __restrict__ bxo) {
    extern __shared__ float sm[];
    float* Xs     = sm;                    // 128*260
    float* Ws     = Xs + 128 * XS_LD;      // 8192
    float* We0h   = Ws + 8192;             // 2048
    float* Wxo_s  = We0h + 2048;           // 8*260 (transposed [h][c])
    float* Winf_s = Wxo_s + 8 * XS_LD;     // 256
    float* sqn_s  = Winf_s + 256;          // 1024  [il][jl][h]
    float* xi_s   = sqn_s + 1024;          // 192
    float* xj_s   = xi_s + 192;            // 384
    float* mi_s   = xj_s + 384;            // 2048  [il][c]
    float* shift_s = mi_s + 2048;          // 192   [il][h][3]

    int tid = threadIdx.x;
    int lane = tid & 31;
    int wid = tid >> 5;
    int jt = blockIdx.x, it = blockIdx.y;
    int it8 = it * 8, jt16 = jt * 16;

    for (int i = tid; i < 2048; i += 512) We0h[i] = We0[i];                 // rows 0..7
    for (int i = tid; i < 2048; i += 512) {
        int c = i >> 3, h2 = i & 7;
        Wxo_s[h2 * XS_LD + c] = Wxo[c * 8 + h2];
    }
    if (tid < 256) Winf_s[tid] = Winf[tid];
    for (int i = tid; i < 192; i += 512) xi_s[i] = x[it8 * 24 + i];
    for (int i = tid; i < 384; i += 512) xj_s[i] = x[jt16 * 24 + i];
    for (int i = tid; i < 2048; i += 512) mi_s[i] = 0.f;
    if (tid < 192) shift_s[tid] = 0.f;
    __syncthreads();

    // pairwise per-head squared distances
    for (int idx = tid; idx < 1024; idx += 512) {
        int il = idx >> 7, rem = idx & 127, jl = rem >> 3, hh = rem & 7;
        float dx = xj_s[(jl * 8 + hh) * 3 + 0] - xi_s[(il * 8 + hh) * 3 + 0];
        float dy = xj_s[(jl * 8 + hh) * 3 + 1] - xi_s[(il * 8 + hh) * 3 + 1];
        float dz = xj_s[(jl * 8 + hh) * 3 + 2] - xi_s[(il * 8 + hh) * 3 + 2];
        sqn_s[idx] = dx * dx + dy * dy + dz * dz;
    }
    __syncthreads();

    // first layer via factorization: h1 = silu(sqn@We0[0:8] + A[j] + B[i] + be0)
    for (int idx = tid; idx < 128 * 256; idx += 512) {
        int e = idx >> 8, c = idx & 255;
        int il = e >> 4, jl = e & 15;
        float v = be0[c] + g_AB[(jt16 + jl) * 512 + c] + g_AB[(it8 + il) * 512 + 256 + c];
        const float* sq = sqn_s + e * 8;
#pragma unroll
        for (int hh = 0; hh < 8; hh++) v += sq[hh] * We0h[hh * 256 + c];
        Xs[e * XS_LD + c] = fsilu(v);
    }

    float acc[8][8];
    int xrow = wid * 8;
    int il0 = wid >> 1;
    int gi = it8 + il0;

    // ---- layer: m = silu(h1@We1 + be1) * off ----
    gemm_tile(We1, Xs, Ws, acc, tid, lane, xrow);
    {
        float bl[8];
#pragma unroll
        for (int jj = 0; jj < 8; jj++) bl[jj] = be1[lane + 32 * jj];
#pragma unroll
        for (int r = 0; r < 8; r++) {
            int gj = jt16 + (wid & 1) * 8 + r;
            float msk = (gi == gj) ? 0.f : 1.f;
#pragma unroll
            for (int jj = 0; jj < 8; jj++) acc[r][jj] = fsilu(acc[r][jj] + bl[jj]) * msk;
        }
        // gate e = sigmoid(m . Winf + binf)
        float binf0 = binf[0];
        float eg[8];
#pragma unroll
        for (int r = 0; r < 8; r++) {
            float s = 0.f;
#pragma unroll
            for (int jj = 0; jj < 8; jj++) s += acc[r][jj] * Winf_s[lane + 32 * jj];
#pragma unroll
            for (int off = 16; off > 0; off >>= 1) s += __shfl_xor_sync(0xffffffffu, s, off);
            eg[r] = 1.0f / (1.0f + __expf(-(s + binf0)));
        }
        // m_i partial aggregation
#pragma unroll
        for (int jj = 0; jj < 8; jj++) {
            float s = 0.f;
#pragma unroll
            for (int r = 0; r < 8; r++) s += eg[r] * acc[r][jj];
            atomicAdd(&mi_s[il0 * 256 + lane + 32 * jj], s);
        }
        // writeback m as next activation
#pragma unroll
        for (int r = 0; r < 8; r++)
#pragma unroll
            for (int jj = 0; jj < 8; jj++) Xs[(xrow + r) * XS_LD + lane + 32 * jj] = acc[r][jj];
    }

    // ---- layer: t0 = silu(m@Wx0 + bx0) ----
    gemm_tile(Wx0, Xs, Ws, acc, tid, lane, xrow);
    {
        float bl[8];
#pragma unroll
        for (int jj = 0; jj < 8; jj++) bl[jj] = bx0[lane + 32 * jj];
#pragma unroll
        for (int r = 0; r < 8; r++)
#pragma unroll
            for (int jj = 0; jj < 8; jj++) acc[r][jj] = fsilu(acc[r][jj] + bl[jj]);
#pragma unroll
        for (int r = 0; r < 8; r++)
#pragma unroll
            for (int jj = 0; jj < 8; jj++) Xs[(xrow + r) * XS_LD + lane + 32 * jj] = acc[r][jj];
    }

    // ---- layer: t1 = silu(t0@Wx1 + bx1); px = t1@Wxo + bxo; shift accumulation ----
    gemm_tile(Wx1, Xs, Ws, acc, tid, lane, xrow);
    {
        float bl[8];
#pragma unroll
        for (int jj = 0; jj < 8; jj++) bl[jj] = bx1[lane + 32 * jj];
#pragma unroll
        for (int r = 0; r < 8; r++)
#pragma unroll
            for (int jj = 0; jj < 8; jj++) acc[r][jj] = fsilu(acc[r][jj] + bl[jj]);

#pragma unroll
        for (int hh = 0; hh < 8; ++hh) {
            float bx = bxo[hh];
            float wv[8];
#pragma unroll
            for (int jj = 0; jj < 8; jj++) wv[jj] = Wxo_s[hh * XS_LD + lane + 32 * jj];
#pragma unroll
            for (int r = 0; r < 8; r++) {
                float s = 0.f;
#pragma unroll
                for (int jj = 0; jj < 8; jj++) s += acc[r][jj] * wv[jj];
#pragma unroll
                for (int off = 16; off > 0; off >>= 1) s += __shfl_xor_sync(0xffffffffu, s, off);
                if (lane == r) {
                    int jl = (wid & 1) * 8 + r;
                    int gj = jt16 + jl;
                    if (gi != gj) {
                        float pxv = s + bx;
                        float d2 = sqn_s[(il0 * 16 + jl) * 8 + hh];
                        float wgt = pxv / (sqrtf(d2 + 1e-8f) + 1.0f);
#pragma unroll
                        for (int d = 0; d < 3; d++)
                            atomicAdd(&shift_s[(il0 * 8 + hh) * 3 + d],
                                      wgt * (xj_s[(jl * 8 + hh) * 3 + d] - xi_s[(il0 * 8 + hh) * 3 + d]));
                    }
                }
            }
        }
    }

    __syncthreads();
    for (int i = tid; i < 2048; i += 512)
        atomicAdd(&g_mi[(it8 + (i >> 8)) * 256 + (i & 255)], mi_s[i]);
    if (tid < 192) atomicAdd(&g_shift[it8 * 24 + tid], shift_s[tid]);
}

// ---------------- finalize: x_new + phi_h input ----------------
__global__ void k_finalize(const float* __restrict__ x, const float* __restrict__ h,
                           float* __restrict__ out_x) {
    int idx = blockIdx.x * blockDim.x + threadIdx.x;
    int stride = gridDim.x * blockDim.x;
    for (int i = idx; i < 512 * 384; i += stride) {
        int n = i / 384, c = i % 384;
        g_phin[i] = (c < 256) ? g_mi[n * 256 + c] : h[n * 128 + (c - 256)];
    }
    for (int i = idx; i < 12288; i += stride)
        out_x[i] = x[i] + g_shift[i] * (1.0f / 511.0f);
}

// ---------------- launch ----------------
extern "C" void kernel_launch(void* const* d_in, const int* in_sizes, int n_in,
                              void* d_out, int out_size) {
    (void)in_sizes; (void)n_in; (void)out_size;
    const float* x    = (const float*)d_in[0];
    const float* h    = (const float*)d_in[1];
    const float* We0  = (const float*)d_in[2];
    const float* be0  = (const float*)d_in[3];
    const float* We1  = (const float*)d_in[4];
    const float* be1  = (const float*)d_in[5];
    const float* Winf = (const float*)d_in[6];
    const float* binf = (const float*)d_in[7];
    const float* Wx0  = (const float*)d_in[8];
    const float* bx0  = (const float*)d_in[9];
    const float* Wx1  = (const float*)d_in[10];
    const float* bx1  = (const float*)d_in[11];
    const float* Wxo  = (const float*)d_in[12];
    const float* bxo  = (const float*)d_in[13];
    const float* Wh0  = (const float*)d_in[14];
    const float* bh0  = (const float*)d_in[15];
    const float* Wh1  = (const float*)d_in[16];
    const float* bh1  = (const float*)d_in[17];
    const float* Who  = (const float*)d_in[18];
    const float* bho  = (const float*)d_in[19];
    float* out = (float*)d_out;

    float *p_hc, *p_AB, *p_phin, *p_t0, *p_t1;
    cudaGetSymbolAddress((void**)&p_hc, g_hc);
    cudaGetSymbolAddress((void**)&p_AB, g_AB);
    cudaGetSymbolAddress((void**)&p_phin, g_phin);
    cudaGetSymbolAddress((void**)&p_t0, g_t0);
    cudaGetSymbolAddress((void**)&p_t1, g_t1);

    const int smem_edge = EDGE_SMEM_FLOATS * 4;
    cudaFuncSetAttribute(k_edge, cudaFuncAttributeMaxDynamicSharedMemorySize, smem_edge);

    k_init<<<128, 512>>>();
    k_hc<<<512, 128>>>(x, h);
    // A[j] = hc @ We0[8:200], B[i] = hc @ We0[200:392]  (into g_AB halves)
    gemm64<<<dim3(4, 8), 256>>>(p_hc, 192, We0 + 8 * 256, 256, nullptr, nullptr, 0,
                                p_AB, 512, 512, 256, 192, 0);
    gemm64<<<dim3(4, 8), 256>>>(p_hc, 192, We0 + 200 * 256, 256, nullptr, nullptr, 0,
                                p_AB + 256, 512, 512, 256, 192, 0);
    k_edge<<<dim3(32, 64), 512, smem_edge>>>(x, We0, be0, We1, be1, Winf, binf,
                                             Wx0, bx0, Wx1, bx1, Wxo, bxo);
    k_finalize<<<256, 512>>>(x, h, out);
    // phi_h
    gemm64<<<dim3(4, 8), 256>>>(p_phin, 384, Wh0, 256, bh0, nullptr, 0,
                                p_t0, 256, 512, 256, 384, 1);
    gemm64<<<dim3(4, 8), 256>>>(p_t0, 256, Wh1, 256, bh1, nullptr, 0,
                                p_t1, 256, 512, 256, 256, 1);
    gemm64<<<dim3(2, 8), 256>>>(p_t1, 256, Who, 128, bho, h, 128,
                                out + 12288, 128, 512, 128, 256, 0);
}

// round 15
// speedup vs baseline: 2.2605x; 2.2605x over previous
#include <cuda_runtime.h>
#include <cuda_bf16.h>
#include <cstdint>

// ---------------- scratch (no allocations allowed) ----------------
__device__ float g_hc[512 * 192];
__device__ float g_AB[512 * 512];    // cols 0..255: A[j]=hc@We0[8:200]; 256..511: B[i]=hc@We0[200:392]
__device__ float g_mi[512 * 256];
__device__ float g_shift[512 * 24];
__device__ float g_phin[512 * 384];
__device__ float g_t0[512 * 256];
__device__ float g_t1[512 * 256];
// weight hi/lo images: [layer(3)][chunk(4)][n(256)][k64 swizzled]
__device__ __align__(16) __nv_bfloat16 g_Whi[196608];
__device__ __align__(16) __nv_bfloat16 g_Wlo[196608];

__device__ __forceinline__ float fsilu(float v) { return v * (1.0f / (1.0f + __expf(-v))); }
__device__ __forceinline__ float fsigm(float v) { return 1.0f / (1.0f + __expf(-v)); }

// ---------------- init: zero accumulators ----------------
__global__ void k_init() {
    int idx = blockIdx.x * blockDim.x + threadIdx.x;
    int stride = gridDim.x * blockDim.x;
    for (int i = idx; i < 512 * 256; i += stride) g_mi[i] = 0.f;
    for (int i = idx; i < 512 * 24; i += stride) g_shift[i] = 0.f;
}

// ---------------- hc = [h | per-node head-pair sq dists] ----------------
__global__ void k_hc(const float* __restrict__ x, const float* __restrict__ h) {
    int n = blockIdx.x;
    __shared__ float xs[24];
    int tid = threadIdx.x;   // 128 threads
    if (tid < 24) xs[tid] = x[n * 24 + tid];
    __syncthreads();
    g_hc[n * 192 + tid] = h[n * 128 + tid];
    if (tid < 64) {
        int a = tid >> 3, b = tid & 7;
        float dx = xs[a * 3 + 0] - xs[b * 3 + 0];
        float dy = xs[a * 3 + 1] - xs[b * 3 + 1];
        float dz = xs[a * 3 + 2] - xs[b * 3 + 2];
        g_hc[n * 192 + 128 + tid] = dx * dx + dy * dy + dz * dz;
    }
}

// ---------------- weight hi/lo decomposition into swizzled images ----------------
__global__ void k_wprep(const float* __restrict__ We1, const float* __restrict__ Wx0,
                        const float* __restrict__ Wx1) {
    int idx = blockIdx.x * blockDim.x + threadIdx.x;
    if (idx >= 196608) return;
    int n = idx & 255;
    int t = idx >> 8;           // lc*64 + kl
    int kl = t & 63;
    int lc = t >> 6;            // l*4 + c
    int c = lc & 3, l = lc >> 2;
    const float* W = (l == 0) ? We1 : ((l == 1) ? Wx0 : Wx1);
    float w = W[(c * 64 + kl) * 256 + n];
    __nv_bfloat16 hi = __float2bfloat16_rn(w);
    float lof = w - __bfloat162float(hi);
    int pos = (((kl >> 3) ^ (n & 7)) << 3) + (kl & 7);
    int o = (lc * 256 + n) * 64 + pos;
    g_Whi[o] = hi;
    g_Wlo[o] = __float2bfloat16_rn(lof);
}

// ---------------- generic small GEMM (node-side) ----------------
__global__ void gemm64(const float* __restrict__ A, int lda,
                       const float* __restrict__ W, int ldw,
                       const float* __restrict__ bias,
                       const float* __restrict__ resid, int ldr,
                       float* __restrict__ out, int ldc,
                       int M, int N, int K, int act) {
    __shared__ float As[16][68];
    __shared__ float Bs[16][68];
    int m0 = blockIdx.y * 64, n0 = blockIdx.x * 64;
    int tid = threadIdx.x;
    int tm = tid >> 4, tn = tid & 15;
    float acc[4][4] = {};
    for (int k0 = 0; k0 < K; k0 += 16) {
#pragma unroll
        for (int u = 0; u < 4; u++) {
            int idx = tid + u * 256;
            int m = idx >> 4, kk = idx & 15;
            As[kk][m] = A[(m0 + m) * lda + k0 + kk];
            int kk2 = idx >> 6, c = idx & 63;
            Bs[kk2][c] = W[(k0 + kk2) * ldw + n0 + c];
        }
        __syncthreads();
#pragma unroll
        for (int kk = 0; kk < 16; kk++) {
            float a[4], b[4];
#pragma unroll
            for (int i = 0; i < 4; i++) a[i] = As[kk][tm * 4 + i];
#pragma unroll
            for (int i = 0; i < 4; i++) b[i] = Bs[kk][tn * 4 + i];
#pragma unroll
            for (int i = 0; i < 4; i++)
#pragma unroll
                for (int j = 0; j < 4; j++) acc[i][j] = fmaf(a[i], b[j], acc[i][j]);
        }
        __syncthreads();
    }
#pragma unroll
    for (int i = 0; i < 4; i++) {
        int row = m0 + tm * 4 + i;
#pragma unroll
        for (int j = 0; j < 4; j++) {
            int col = n0 + tn * 4 + j;
            float v = acc[i][j];
            if (bias) v += bias[col];
            if (act) v = fsilu(v);
            if (resid) v += resid[row * ldr + col];
            out[row * ldc + col] = v;
        }
    }
}

// ---------------- tensor-core fused edge kernel ----------------
// SMEM layout (byte offsets)
#define SM_ACT_HI 0         // 128 x 256 bf16 swizzled (65536)
#define SM_ACT_LO 65536     // 65536
#define SM_W_HI   131072    // 256 x 64 bf16 chunk (32768)
#define SM_W_LO   163840    // 32768
#define SM_UNION  196608    // phase1: We0h fp32 [8][256] (8192); later px_s [128][8]
#define SM_WXO    204800    // Wxo fp32 [256][8] (8192)
#define SM_WINF   212992    // 1024
#define SM_SQN    214016    // [128 e][8 h] f32 (4096)
#define SM_XI     218112    // 768
#define SM_XJ     218880    // 1536
#define SM_GATE   220416    // 512
#define SM_SHIFT  220928    // 768
#define SM_TOTAL  221696

__device__ __forceinline__ void ldsm4(uint32_t r[4], uint32_t addr) {
    asm volatile("ldmatrix.sync.aligned.m8n8.x4.shared.b16 {%0,%1,%2,%3}, [%4];\n"
                 : "=r"(r[0]), "=r"(r[1]), "=r"(r[2]), "=r"(r[3]) : "r"(addr));
}

__device__ __forceinline__ void mma_bf16(float d[4], const uint32_t a[4], uint32_t b0, uint32_t b1) {
    asm volatile("mma.sync.aligned.m16n8k16.row.col.f32.bf16.bf16.f32 "
                 "{%0,%1,%2,%3}, {%4,%5,%6,%7}, {%8,%9}, {%0,%1,%2,%3};\n"
                 : "+f"(d[0]), "+f"(d[1]), "+f"(d[2]), "+f"(d[3])
                 : "r"(a[0]), "r"(a[1]), "r"(a[2]), "r"(a[3]), "r"(b0), "r"(b1));
}

__device__ __forceinline__ void packpair(float v0, float v1, uint32_t& hi, uint32_t& lo) {
    __nv_bfloat16 h0 = __float2bfloat16_rn(v0), h1 = __float2bfloat16_rn(v1);
    float r0 = v0 - __bfloat162float(h0), r1 = v1 - __bfloat162float(h1);
    __nv_bfloat16 l0 = __float2bfloat16_rn(r0), l1 = __float2bfloat16_rn(r1);
    hi = (uint32_t)__bfloat16_as_ushort(h0) | ((uint32_t)__bfloat16_as_ushort(h1) << 16);
    lo = (uint32_t)__bfloat16_as_ushort(l0) | ((uint32_t)__bfloat16_as_ushort(l1) << 16);
}

// One 256x256 layer: acc = 3-term bf16 MMA of act[128x256] @ W[256x256] (this warp's 16Mx128N slab)
__device__ __forceinline__ void mma_layer(char* sm, uint32_t sbase,
                                          const __nv_bfloat16* __restrict__ WgHi,
                                          const __nv_bfloat16* __restrict__ WgLo,
                                          float (&acc)[16][4], int tid, int lane, int wid) {
    const int hf = wid & 1;
    const int il = wid >> 1;
    const int q = lane >> 3, lr = lane & 7;
    const int kqh = q >> 1, kq1 = q & 1;
    const int eA = il * 16 + lr + ((q & 1) << 3);
    const uint32_t preA = sbase + SM_ACT_HI + eA * 512;
    const int e7 = eA & 7;
    const int nB = hf * 128 + lr + (kqh << 3);
    const uint32_t preB = sbase + SM_W_HI + nB * 128;
    const int n7 = lr;
#pragma unroll
    for (int nt = 0; nt < 16; nt++)
#pragma unroll
        for (int i = 0; i < 4; i++) acc[nt][i] = 0.f;

    for (int c = 0; c < 4; c++) {
        __syncthreads();
        const float4* srcH = reinterpret_cast<const float4*>(WgHi + c * 16384);
        const float4* srcL = reinterpret_cast<const float4*>(WgLo + c * 16384);
        float4* dstH = reinterpret_cast<float4*>(sm + SM_W_HI);
        float4* dstL = reinterpret_cast<float4*>(sm + SM_W_LO);
#pragma unroll
        for (int u = 0; u < 4; u++) {
            dstH[tid + u * 512] = srcH[tid + u * 512];
            dstL[tid + u * 512] = srcL[tid + u * 512];
        }
        __syncthreads();
#pragma unroll
        for (int ks = 0; ks < 4; ks++) {
            uint32_t ah[4], al[4];
            uint32_t aAddr = preA + (uint32_t)((((c << 3) + (ks << 1) + kqh) ^ e7) << 4);
            ldsm4(ah, aAddr);
            ldsm4(al, aAddr + 65536);
            uint32_t bAddr0 = preB + (uint32_t)((((ks << 1) + kq1) ^ n7) << 4);
#pragma unroll
            for (int p = 0; p < 8; p++) {
                uint32_t bh[4], bl[4];
                ldsm4(bh, bAddr0 + p * 2048);
                ldsm4(bl, bAddr0 + p * 2048 + 32768);
                mma_bf16(acc[2 * p],     ah, bh[0], bh[1]);
                mma_bf16(acc[2 * p + 1], ah, bh[2], bh[3]);
                mma_bf16(acc[2 * p],     al, bh[0], bh[1]);
                mma_bf16(acc[2 * p + 1], al, bh[2], bh[3]);
                mma_bf16(acc[2 * p],     ah, bl[0], bl[1]);
                mma_bf16(acc[2 * p + 1], ah, bl[2], bl[3]);
            }
        }
    }
}

__global__ __launch_bounds__(512, 1) void k_edge(
    const float* __restrict__ x,
    const float* __restrict__ We0, const float* __restrict__ be0,
    const float* __restrict__ be1,
    const float* __restrict__ Winf, const float* __restrict__ binf,
    const float* __restrict__ bx0, const float* __restrict__ bx1,
    const float* __restrict__ Wxo, const float* __restrict__ bxo) {
    extern __shared__ char sm[];
    const int tid = threadIdx.x, lane = tid & 31, wid = tid >> 5;
    const int g = lane >> 2, tig = lane & 3;
    const int jt16 = blockIdx.x * 16, it8 = blockIdx.y * 8;

    float* We0h = (float*)(sm + SM_UNION);
    float* Wxo_s = (float*)(sm + SM_WXO);
    float* Winf_s = (float*)(sm + SM_WINF);
    float* sqn_s = (float*)(sm + SM_SQN);
    float* xi_s = (float*)(sm + SM_XI);
    float* xj_s = (float*)(sm + SM_XJ);
    float* gate_s = (float*)(sm + SM_GATE);
    float* shift_s = (float*)(sm + SM_SHIFT);
    char* actHi = sm + SM_ACT_HI;
    char* actLo = sm + SM_ACT_LO;
    uint32_t sbase = (uint32_t)__cvta_generic_to_shared(sm);

    for (int i = tid; i < 2048; i += 512) We0h[i] = We0[i];   // rows 0..7 of We0
    for (int i = tid; i < 2048; i += 512) Wxo_s[i] = Wxo[i];  // [c][h] row-major
    if (tid < 256) Winf_s[tid] = Winf[tid];
    for (int i = tid; i < 192; i += 512) xi_s[i] = x[it8 * 24 + i];
    for (int i = tid; i < 384; i += 512) xj_s[i] = x[jt16 * 24 + i];
    if (tid < 128) gate_s[tid] = 0.f;
    if (tid < 192) shift_s[tid] = 0.f;
    __syncthreads();

    // pairwise per-head squared distances [e = il*16+jl][h]
    for (int idx = tid; idx < 1024; idx += 512) {
        int il2 = idx >> 7, rem = idx & 127, jl2 = rem >> 3, hh = rem & 7;
        float dx = xj_s[(jl2 * 8 + hh) * 3 + 0] - xi_s[(il2 * 8 + hh) * 3 + 0];
        float dy = xj_s[(jl2 * 8 + hh) * 3 + 1] - xi_s[(il2 * 8 + hh) * 3 + 1];
        float dz = xj_s[(jl2 * 8 + hh) * 3 + 2] - xi_s[(il2 * 8 + hh) * 3 + 2];
        sqn_s[idx] = dx * dx + dy * dy + dz * dz;
    }
    __syncthreads();

    // phase 1: act = silu(be0 + A[j] + B[i] + sqn@We0[0:8]) -> swizzled bf16 hi/lo
    for (int i = tid; i < 16384; i += 512) {
        int e = i >> 7, cp = (i & 127) << 1;
        int il2 = e >> 4, jl2 = e & 15;
        const float* rA = g_AB + (jt16 + jl2) * 512;
        const float* rB = g_AB + (it8 + il2) * 512 + 256;
        float v0 = __ldg(be0 + cp) + rA[cp] + rB[cp];
        float v1 = __ldg(be0 + cp + 1) + rA[cp + 1] + rB[cp + 1];
        const float* sq = sqn_s + e * 8;
#pragma unroll
        for (int hh = 0; hh < 8; hh++) {
            float s = sq[hh];
            v0 += s * We0h[hh * 256 + cp];
            v1 += s * We0h[hh * 256 + cp + 1];
        }
        v0 = fsilu(v0); v1 = fsilu(v1);
        uint32_t ph, pl;
        packpair(v0, v1, ph, pl);
        int byte = e * 512 + ((((cp >> 3) ^ (e & 7))) << 4) + ((cp & 7) << 1);
        *(uint32_t*)(actHi + byte) = ph;
        *(uint32_t*)(actLo + byte) = pl;
    }
    __syncthreads();
    float* px_s = (float*)(sm + SM_UNION);   // reuse We0h space (done with it)
    for (int i = tid; i < 1024; i += 512) px_s[i] = 0.f;

    const int il = wid >> 1, hf = wid & 1, e0 = il * 16;
    const int gi = it8 + il;
    float acc[16][4];

    // ================= layer 1: m = silu(h1@We1+be1)*off; gate; m_i =================
    mma_layer(sm, sbase, g_Whi, g_Wlo, acc, tid, lane, wid);
    {
        float msk0 = (gi == jt16 + g) ? 0.f : 1.f;
        float msk1 = (gi == jt16 + g + 8) ? 0.f : 1.f;
        float gp0 = 0.f, gp1 = 0.f;
#pragma unroll
        for (int nt = 0; nt < 16; nt++) {
            int colb = hf * 128 + nt * 8 + tig * 2;
            float b0 = __ldg(be1 + colb), b1 = __ldg(be1 + colb + 1);
            acc[nt][0] = fsilu(acc[nt][0] + b0) * msk0;
            acc[nt][1] = fsilu(acc[nt][1] + b1) * msk0;
            acc[nt][2] = fsilu(acc[nt][2] + b0) * msk1;
            acc[nt][3] = fsilu(acc[nt][3] + b1) * msk1;
            float w0 = Winf_s[colb], w1 = Winf_s[colb + 1];
            gp0 += acc[nt][0] * w0 + acc[nt][1] * w1;
            gp1 += acc[nt][2] * w0 + acc[nt][3] * w1;
        }
        gp0 += __shfl_xor_sync(~0u, gp0, 1); gp0 += __shfl_xor_sync(~0u, gp0, 2);
        gp1 += __shfl_xor_sync(~0u, gp1, 1); gp1 += __shfl_xor_sync(~0u, gp1, 2);
        if (tig == 0) {
            atomicAdd(&gate_s[e0 + g], gp0);
            atomicAdd(&gate_s[e0 + g + 8], gp1);
        }
        __syncthreads();   // gate complete; all MMA act-reads done -> safe to overwrite act
        float binf0 = __ldg(binf);
        float gate0 = fsigm(gate_s[e0 + g] + binf0);
        float gate1 = fsigm(gate_s[e0 + g + 8] + binf0);
#pragma unroll
        for (int nt = 0; nt < 16; nt++) {
            int colb = hf * 128 + nt * 8 + tig * 2;
            float s0 = acc[nt][0] * gate0 + acc[nt][2] * gate1;
            float s1 = acc[nt][1] * gate0 + acc[nt][3] * gate1;
            s0 += __shfl_xor_sync(~0u, s0, 16); s0 += __shfl_xor_sync(~0u, s0, 8); s0 += __shfl_xor_sync(~0u, s0, 4);
            s1 += __shfl_xor_sync(~0u, s1, 16); s1 += __shfl_xor_sync(~0u, s1, 8); s1 += __shfl_xor_sync(~0u, s1, 4);
            if (lane < 4) {
                atomicAdd(&g_mi[(it8 + il) * 256 + colb], s0);
                atomicAdd(&g_mi[(it8 + il) * 256 + colb + 1], s1);
            }
            uint32_t ph, pl;
            packpair(acc[nt][0], acc[nt][1], ph, pl);
            int r0 = e0 + g;
            int byte0 = r0 * 512 + ((((colb >> 3) ^ (r0 & 7))) << 4) + ((colb & 7) << 1);
            *(uint32_t*)(actHi + byte0) = ph;
            *(uint32_t*)(actLo + byte0) = pl;
            packpair(acc[nt][2], acc[nt][3], ph, pl);
            int r1 = e0 + g + 8;
            int byte1 = r1 * 512 + ((((colb >> 3) ^ (r1 & 7))) << 4) + ((colb & 7) << 1);
            *(uint32_t*)(actHi + byte1) = ph;
            *(uint32_t*)(actLo + byte1) = pl;
        }
    }

    // ================= layer 2: t0 = silu(m@Wx0+bx0) =================
    mma_layer(sm, sbase, g_Whi + 65536, g_Wlo + 65536, acc, tid, lane, wid);
    {
        __syncthreads();   // all MMA act-reads done before overwrite
#pragma unroll
        for (int nt = 0; nt < 16; nt++) {
            int colb = hf * 128 + nt * 8 + tig * 2;
            float b0 = __ldg(bx0 + colb), b1 = __ldg(bx0 + colb + 1);
            float v0 = fsilu(acc[nt][0] + b0);
            float v1 = fsilu(acc[nt][1] + b1);
            float v2 = fsilu(acc[nt][2] + b0);
            float v3 = fsilu(acc[nt][3] + b1);
            uint32_t ph, pl;
            packpair(v0, v1, ph, pl);
            int r0 = e0 + g;
            int byte0 = r0 * 512 + ((((colb >> 3) ^ (r0 & 7))) << 4) + ((colb & 7) << 1);
            *(uint32_t*)(actHi + byte0) = ph;
            *(uint32_t*)(actLo + byte0) = pl;
            packpair(v2, v3, ph, pl);
            int r1 = e0 + g + 8;
            int byte1 = r1 * 512 + ((((colb >> 3) ^ (r1 & 7))) << 4) + ((colb & 7) << 1);
            *(uint32_t*)(actHi + byte1) = ph;
            *(uint32_t*)(actLo + byte1) = pl;
        }
    }

    // ================= layer 3: t1 = silu(t0@Wx1+bx1); px = t1@Wxo+bxo; shift =================
    mma_layer(sm, sbase, g_Whi + 131072, g_Wlo + 131072, acc, tid, lane, wid);
    {
#pragma unroll
        for (int nt = 0; nt < 16; nt++) {
            int colb = hf * 128 + nt * 8 + tig * 2;
            float b0 = __ldg(bx1 + colb), b1 = __ldg(bx1 + colb + 1);
            acc[nt][0] = fsilu(acc[nt][0] + b0);
            acc[nt][1] = fsilu(acc[nt][1] + b1);
            acc[nt][2] = fsilu(acc[nt][2] + b0);
            acc[nt][3] = fsilu(acc[nt][3] + b1);
        }
#pragma unroll
        for (int hh = 0; hh < 8; hh++) {
            float s0 = 0.f, s1 = 0.f;
#pragma unroll
            for (int nt = 0; nt < 16; nt++) {
                int colb = hf * 128 + nt * 8 + tig * 2;
                float w0 = Wxo_s[colb * 8 + hh], w1 = Wxo_s[(colb + 1) * 8 + hh];
                s0 += acc[nt][0] * w0 + acc[nt][1] * w1;
                s1 += acc[nt][2] * w0 + acc[nt][3] * w1;
            }
            s0 += __shfl_xor_sync(~0u, s0, 1); s0 += __shfl_xor_sync(~0u, s0, 2);
            s1 += __shfl_xor_sync(~0u, s1, 1); s1 += __shfl_xor_sync(~0u, s1, 2);
            if (tig == 0) {
                atomicAdd(&px_s[(e0 + g) * 8 + hh], s0);
                atomicAdd(&px_s[(e0 + g + 8) * 8 + hh], s1);
            }
        }
        __syncthreads();
        for (int idx = tid; idx < 1024; idx += 512) {
            int e = idx >> 3, hh = idx & 7;
            int il2 = e >> 4, jl2 = e & 15;
            if (it8 + il2 != jt16 + jl2) {
                float pxv = px_s[idx] + __ldg(bxo + hh);
                float d2 = sqn_s[e * 8 + hh];
                float wgt = pxv / (sqrtf(d2 + 1e-8f) + 1.0f);
#pragma unroll
                for (int d = 0; d < 3; d++)
                    atomicAdd(&shift_s[(il2 * 8 + hh) * 3 + d],
                              wgt * (xj_s[(jl2 * 8 + hh) * 3 + d] - xi_s[(il2 * 8 + hh) * 3 + d]));
            }
        }
        __syncthreads();
        if (tid < 192) atomicAdd(&g_shift[it8 * 24 + tid], shift_s[tid]);
    }
}

// ---------------- finalize: x_new + phi_h input ----------------
__global__ void k_finalize(const float* __restrict__ x, const float* __restrict__ h,
                           float* __restrict__ out_x) {
    int idx = blockIdx.x * blockDim.x + threadIdx.x;
    int stride = gridDim.x * blockDim.x;
    for (int i = idx; i < 512 * 384; i += stride) {
        int n = i / 384, c = i % 384;
        g_phin[i] = (c < 256) ? g_mi[n * 256 + c] : h[n * 128 + (c - 256)];
    }
    for (int i = idx; i < 12288; i += stride)
        out_x[i] = x[i] + g_shift[i] * (1.0f / 511.0f);
}

// ---------------- launch ----------------
extern "C" void kernel_launch(void* const* d_in, const int* in_sizes, int n_in,
                              void* d_out, int out_size) {
    (void)in_sizes; (void)n_in; (void)out_size;
    const float* x    = (const float*)d_in[0];
    const float* h    = (const float*)d_in[1];
    const float* We0  = (const float*)d_in[2];
    const float* be0  = (const float*)d_in[3];
    const float* We1  = (const float*)d_in[4];
    const float* be1  = (const float*)d_in[5];
    const float* Winf = (const float*)d_in[6];
    const float* binf = (const float*)d_in[7];
    const float* Wx0  = (const float*)d_in[8];
    const float* bx0  = (const float*)d_in[9];
    const float* Wx1  = (const float*)d_in[10];
    const float* bx1  = (const float*)d_in[11];
    const float* Wxo  = (const float*)d_in[12];
    const float* bxo  = (const float*)d_in[13];
    const float* Wh0  = (const float*)d_in[14];
    const float* bh0  = (const float*)d_in[15];
    const float* Wh1  = (const float*)d_in[16];
    const float* bh1  = (const float*)d_in[17];
    const float* Who  = (const float*)d_in[18];
    const float* bho  = (const float*)d_in[19];
    float* out = (float*)d_out;

    float *p_hc, *p_AB, *p_phin, *p_t0, *p_t1;
    cudaGetSymbolAddress((void**)&p_hc, g_hc);
    cudaGetSymbolAddress((void**)&p_AB, g_AB);
    cudaGetSymbolAddress((void**)&p_phin, g_phin);
    cudaGetSymbolAddress((void**)&p_t0, g_t0);
    cudaGetSymbolAddress((void**)&p_t1, g_t1);

    cudaFuncSetAttribute(k_edge, cudaFuncAttributeMaxDynamicSharedMemorySize, SM_TOTAL);

    k_init<<<128, 512>>>();
    k_hc<<<512, 128>>>(x, h);
    k_wprep<<<384, 512>>>(We1, Wx0, Wx1);
    // A[j] = hc @ We0[8:200], B[i] = hc @ We0[200:392]  (into g_AB halves)
    gemm64<<<dim3(4, 8), 256>>>(p_hc, 192, We0 + 8 * 256, 256, nullptr, nullptr, 0,
                                p_AB, 512, 512, 256, 192, 0);
    gemm64<<<dim3(4, 8), 256>>>(p_hc, 192, We0 + 200 * 256, 256, nullptr, nullptr, 0,
                                p_AB + 256, 512, 512, 256, 192, 0);
    k_edge<<<dim3(32, 64), 512, SM_TOTAL>>>(x, We0, be0, be1, Winf, binf,
                                            bx0, bx1, Wxo, bxo);
    k_finalize<<<256, 512>>>(x, h, out);
    // phi_h
    gemm64<<<dim3(4, 8), 256>>>(p_phin, 384, Wh0, 256, bh0, nullptr, 0,
                                p_t0, 256, 512, 256, 384, 1);
    gemm64<<<dim3(4, 8), 256>>>(p_t0, 256, Wh1, 256, bh1, nullptr, 0,
                                p_t1, 256, 512, 256, 256, 1);
    gemm64<<<dim3(2, 8), 256>>>(p_t1, 256, Who, 128, bho, h, 128,
                                out + 12288, 128, 512, 128, 256, 0);
}